// round 3
// baseline (speedup 1.0000x reference)
#include <cuda_runtime.h>
#include <math.h>

#define D 256
#define N_SEQ 2048
#define NB 16
#define NTOK (NB*N_SEQ)

// -------- scratch (device globals: allocation-guard safe) --------
__device__ float g_s4[NTOK*4];            // (s0,s1,s2,|s|^2) per token
__device__ float g_msg[NTOK*D];           // relu(x@w_msg^T+b)
__device__ float g_h1[NTOK*D];            // conv1+bn1+relu, token-major
__device__ float g_xin[(size_t)NTOK*2*D]; // [x_conv | x_nmp]
__device__ float g_gi[(size_t)NTOK*3*D];
__device__ float g_gh[(size_t)NTOK*3*D];
__device__ float g_w2p[D*D*17];           // conv2_w repacked (o,k,i)

// -------- repack conv2 weights (o,i,k) -> (o,k,i) --------
__global__ void repack_w2(const float* __restrict__ w) {
    int idx = blockIdx.x*256 + threadIdx.x;
    if (idx < D*D*17) {
        int o = idx/(D*17); int r = idx%(D*17); int k = r/D; int i = r%D;
        g_w2p[idx] = w[(size_t)o*D*17 + (size_t)i*17 + k];
    }
}

// -------- s embedding: s = x@w_se^T + b_se ; also |s|^2 --------
__global__ void se_kernel(const float* __restrict__ x,
                          const float* __restrict__ w_se,
                          const float* __restrict__ b_se) {
    int tok = blockIdx.x*8 + (threadIdx.x>>5);
    int lane = threadIdx.x & 31;
    const float* xp = x + (size_t)tok*D;
    float d0=0.f, d1=0.f, d2=0.f;
    #pragma unroll
    for (int i=lane; i<D; i+=32) {
        float xv = xp[i];
        d0 += xv * w_se[i];
        d1 += xv * w_se[D+i];
        d2 += xv * w_se[2*D+i];
    }
    #pragma unroll
    for (int o=16; o; o>>=1) {
        d0 += __shfl_down_sync(0xffffffffu, d0, o);
        d1 += __shfl_down_sync(0xffffffffu, d1, o);
        d2 += __shfl_down_sync(0xffffffffu, d2, o);
    }
    if (lane==0) {
        float s0 = d0 + b_se[0], s1 = d1 + b_se[1], s2 = d2 + b_se[2];
        float4 v = make_float4(s0, s1, s2, s0*s0 + s1*s1 + s2*s2);
        ((float4*)g_s4)[tok] = v;
    }
}

// -------- generic NT SGEMM: C[t,n] = sum_k A[t,k]*W[n,k]  (+epilogue) ----
// MODE 0: conv1 -> bn1+relu
// MODE 1: conv2 (A = shifted h1, K=4352) -> bn2 + residual(x) + relu
// MODE 2: +bias, relu (msg)
// MODE 3: +bias (gi/gh)
template<int MODE>
__global__ __launch_bounds__(256) void nt_gemm(
    const float* __restrict__ A, int lda,
    const float* __restrict__ W,
    float* __restrict__ C, int ldc, int coff,
    int K,
    const float* __restrict__ bias,
    const float* __restrict__ bng, const float* __restrict__ bnb,
    const float* __restrict__ bnm, const float* __restrict__ bnv,
    const float* __restrict__ res)
{
    __shared__ float As[16][132];
    __shared__ float Ws[16][132];

    int b  = blockIdx.z;
    int m0 = blockIdx.y * 128;
    int n0 = blockIdx.x * 128;
    const float* Ab = A + (size_t)b * N_SEQ * lda;

    int tid = threadIdx.x;
    int ty = tid >> 4, tx = tid & 15;
    int ty4 = ty*4, tx4 = tx*4;

    float acc[8][8];
    #pragma unroll
    for (int i=0;i<8;i++)
        #pragma unroll
        for (int j=0;j<8;j++) acc[i][j]=0.f;

    for (int kt = 0; kt < K; kt += 16) {
        #pragma unroll
        for (int r = 0; r < 2; r++) {
            int lin = tid + 256*r;
            int row = lin >> 2;
            int kq  = (lin & 3) * 4;
            float4 v;
            if (MODE == 1) {
                int kk = kt + kq;
                int k  = kk >> 8;      // tap index 0..16
                int i  = kk & 255;     // input channel
                int srct = m0 + row + k - 8;
                if (srct >= 0 && srct < N_SEQ)
                    v = *(const float4*)(Ab + (size_t)srct*D + i);
                else
                    v = make_float4(0.f,0.f,0.f,0.f);
            } else {
                v = *(const float4*)(Ab + (size_t)(m0+row)*lda + kt + kq);
            }
            As[kq+0][row]=v.x; As[kq+1][row]=v.y; As[kq+2][row]=v.z; As[kq+3][row]=v.w;
            float4 w = *(const float4*)(W + (size_t)(n0+row)*K + kt + kq);
            Ws[kq+0][row]=w.x; Ws[kq+1][row]=w.y; Ws[kq+2][row]=w.z; Ws[kq+3][row]=w.w;
        }
        __syncthreads();
        #pragma unroll
        for (int kk = 0; kk < 16; kk++) {
            float av[8], wv[8];
            float4 t;
            t = *(const float4*)&As[kk][ty4];    av[0]=t.x; av[1]=t.y; av[2]=t.z; av[3]=t.w;
            t = *(const float4*)&As[kk][64+ty4]; av[4]=t.x; av[5]=t.y; av[6]=t.z; av[7]=t.w;
            t = *(const float4*)&Ws[kk][tx4];    wv[0]=t.x; wv[1]=t.y; wv[2]=t.z; wv[3]=t.w;
            t = *(const float4*)&Ws[kk][64+tx4]; wv[4]=t.x; wv[5]=t.y; wv[6]=t.z; wv[7]=t.w;
            #pragma unroll
            for (int i=0;i<8;i++)
                #pragma unroll
                for (int j=0;j<8;j++)
                    acc[i][j] += av[i]*wv[j];
        }
        __syncthreads();
    }

    // epilogue
    #pragma unroll
    for (int i = 0; i < 8; i++) {
        int m = m0 + ((i<4) ? (ty4+i) : (64+ty4+i-4));
        #pragma unroll
        for (int jh = 0; jh < 2; jh++) {
            int n = n0 + jh*64 + tx4;
            float v[4];
            #pragma unroll
            for (int jj=0; jj<4; jj++) v[jj] = acc[i][jh*4+jj];
            if (MODE == 0 || MODE == 1) {
                float4 rv = make_float4(0.f,0.f,0.f,0.f);
                if (MODE == 1)
                    rv = *(const float4*)(res + ((size_t)b*N_SEQ + m)*D + n);
                float rr[4] = {rv.x, rv.y, rv.z, rv.w};
                #pragma unroll
                for (int jj=0; jj<4; jj++) {
                    int col = n + jj;
                    float sc = bng[col] * rsqrtf(bnv[col] + 1e-5f);
                    float sh = bnb[col] - bnm[col]*sc;
                    float o = v[jj]*sc + sh + rr[jj];
                    v[jj] = fmaxf(o, 0.f);
                }
            } else if (MODE == 2) {
                #pragma unroll
                for (int jj=0; jj<4; jj++) v[jj] = fmaxf(v[jj] + bias[n+jj], 0.f);
            } else {
                #pragma unroll
                for (int jj=0; jj<4; jj++) v[jj] = v[jj] + bias[n+jj];
            }
            float4 o4 = make_float4(v[0],v[1],v[2],v[3]);
            *(float4*)(C + ((size_t)b*N_SEQ + m)*ldc + coff + n) = o4;
        }
    }
}

// -------- fused NMP: A_ij = exp(-|s_i-s_j|^2)*mask ; x_nmp = A @ msg ------
__global__ __launch_bounds__(256) void nmp_kernel(const float* __restrict__ mask) {
    __shared__ float4 sI[64];
    __shared__ float4 sJ[32];
    __shared__ float  As[64][33];
    __shared__ float  msgS[32*256];

    int b  = blockIdx.y;
    int i0 = blockIdx.x * 64;
    int tid = threadIdx.x;

    if (tid < 64) sI[tid] = ((const float4*)g_s4)[b*N_SEQ + i0 + tid];

    float acc[4][16];
    #pragma unroll
    for (int r=0;r<4;r++)
        #pragma unroll
        for (int q=0;q<16;q++) acc[r][q]=0.f;

    int ip4 = (tid >> 4) * 4;   // 4 i-rows per thread
    int cq4 = (tid & 15) * 4;   // d columns: cq4 + 64*q
    const float* maskb = mask + (size_t)b * N_SEQ * N_SEQ;

    __syncthreads();
    for (int j0 = 0; j0 < N_SEQ; j0 += 32) {
        __syncthreads();  // protect previous iteration's reads
        if (tid < 32) sJ[tid] = ((const float4*)g_s4)[b*N_SEQ + j0 + tid];
        #pragma unroll
        for (int r = 0; r < 8; r++) {
            int lin = tid + r*256;           // 0..2047 float4s
            int row = lin >> 6, c4 = (lin & 63) * 4;
            *(float4*)&msgS[row*256 + c4] =
                *(const float4*)(g_msg + ((size_t)(b*N_SEQ + j0 + row))*D + c4);
        }
        __syncthreads();
        // compute A tile: 64 x 32, 8 entries/thread
        {
            int ii = tid >> 2;
            int jq = (tid & 3) * 8;
            float4 si = sI[ii];
            float4 mk0 = *(const float4*)(maskb + (size_t)(i0+ii)*N_SEQ + j0 + jq);
            float4 mk1 = *(const float4*)(maskb + (size_t)(i0+ii)*N_SEQ + j0 + jq + 4);
            float mk[8] = {mk0.x,mk0.y,mk0.z,mk0.w,mk1.x,mk1.y,mk1.z,mk1.w};
            #pragma unroll
            for (int jj = 0; jj < 8; jj++) {
                float4 sj = sJ[jq+jj];
                float dist = si.w + sj.w - 2.f*(si.x*sj.x + si.y*sj.y + si.z*sj.z);
                As[ii][jq+jj] = __expf(-dist) * mk[jj];
            }
        }
        __syncthreads();
        // acc += A_tile @ msg_tile
        #pragma unroll 4
        for (int j = 0; j < 32; j++) {
            float a0 = As[ip4+0][j];
            float a1 = As[ip4+1][j];
            float a2 = As[ip4+2][j];
            float a3 = As[ip4+3][j];
            #pragma unroll
            for (int q = 0; q < 4; q++) {
                float4 mv = *(const float4*)&msgS[j*256 + cq4 + 64*q];
                acc[0][q*4+0]+=a0*mv.x; acc[0][q*4+1]+=a0*mv.y; acc[0][q*4+2]+=a0*mv.z; acc[0][q*4+3]+=a0*mv.w;
                acc[1][q*4+0]+=a1*mv.x; acc[1][q*4+1]+=a1*mv.y; acc[1][q*4+2]+=a1*mv.z; acc[1][q*4+3]+=a1*mv.w;
                acc[2][q*4+0]+=a2*mv.x; acc[2][q*4+1]+=a2*mv.y; acc[2][q*4+2]+=a2*mv.z; acc[2][q*4+3]+=a2*mv.w;
                acc[3][q*4+0]+=a3*mv.x; acc[3][q*4+1]+=a3*mv.y; acc[3][q*4+2]+=a3*mv.z; acc[3][q*4+3]+=a3*mv.w;
            }
        }
    }

    // write x_nmp into x_in[:, 256:512]
    #pragma unroll
    for (int r = 0; r < 4; r++) {
        size_t rowbase = ((size_t)(b*N_SEQ + i0 + ip4 + r)) * (2*D) + D;
        #pragma unroll
        for (int q = 0; q < 4; q++) {
            float4 o4 = make_float4(acc[r][q*4+0], acc[r][q*4+1], acc[r][q*4+2], acc[r][q*4+3]);
            *(float4*)(g_xin + rowbase + cq4 + 64*q) = o4;
        }
    }
}

// -------- GRU combine --------
__device__ __forceinline__ float sigf(float a){ return 1.f/(1.f + __expf(-a)); }

__global__ void combine_kernel(const float* __restrict__ x, float* __restrict__ out) {
    int idx = blockIdx.x*256 + threadIdx.x;   // float4 index over NTOK*64
    int tok = idx >> 6;
    int c4  = (idx & 63) * 4;
    const float* gi = g_gi + (size_t)tok*3*D;
    const float* gh = g_gh + (size_t)tok*3*D;
    float4 gir = *(const float4*)(gi + c4);
    float4 giz = *(const float4*)(gi + D + c4);
    float4 gin = *(const float4*)(gi + 2*D + c4);
    float4 ghr = *(const float4*)(gh + c4);
    float4 ghz = *(const float4*)(gh + D + c4);
    float4 ghn = *(const float4*)(gh + 2*D + c4);
    float4 xv  = *(const float4*)(x + (size_t)tok*D + c4);
    float4 o;
    {
        float r = sigf(gir.x + ghr.x); float z = sigf(giz.x + ghz.x);
        float nn = tanhf(gin.x + r*ghn.x); o.x = (1.f-z)*nn + z*xv.x;
    }
    {
        float r = sigf(gir.y + ghr.y); float z = sigf(giz.y + ghz.y);
        float nn = tanhf(gin.y + r*ghn.y); o.y = (1.f-z)*nn + z*xv.y;
    }
    {
        float r = sigf(gir.z + ghr.z); float z = sigf(giz.z + ghz.z);
        float nn = tanhf(gin.z + r*ghn.z); o.z = (1.f-z)*nn + z*xv.z;
    }
    {
        float r = sigf(gir.w + ghr.w); float z = sigf(giz.w + ghz.w);
        float nn = tanhf(gin.w + r*ghn.w); o.w = (1.f-z)*nn + z*xv.w;
    }
    *(float4*)(out + (size_t)tok*D + c4) = o;
}

// -------- launch --------
extern "C" void kernel_launch(void* const* d_in, const int* in_sizes, int n_in,
                              void* d_out, int out_size) {
    (void)in_sizes; (void)n_in; (void)out_size;
    const float* x       = (const float*)d_in[0];
    const float* mask    = (const float*)d_in[1];
    const float* w_se    = (const float*)d_in[2];
    const float* b_se    = (const float*)d_in[3];
    const float* conv1_w = (const float*)d_in[4];
    const float* bn1_g   = (const float*)d_in[5];
    const float* bn1_b   = (const float*)d_in[6];
    const float* bn1_m   = (const float*)d_in[7];
    const float* bn1_v   = (const float*)d_in[8];
    const float* conv2_w = (const float*)d_in[9];
    const float* bn2_g   = (const float*)d_in[10];
    const float* bn2_b   = (const float*)d_in[11];
    const float* bn2_m   = (const float*)d_in[12];
    const float* bn2_v   = (const float*)d_in[13];
    const float* w_msg   = (const float*)d_in[14];
    const float* b_msg   = (const float*)d_in[15];
    const float* w_ih    = (const float*)d_in[16];
    const float* b_ih    = (const float*)d_in[17];
    const float* w_hh    = (const float*)d_in[18];
    const float* b_hh    = (const float*)d_in[19];
    float* out = (float*)d_out;

    float *h1p, *msgp, *xinp, *gip, *ghp, *w2pp;
    cudaGetSymbolAddress((void**)&h1p,  g_h1);
    cudaGetSymbolAddress((void**)&msgp, g_msg);
    cudaGetSymbolAddress((void**)&xinp, g_xin);
    cudaGetSymbolAddress((void**)&gip,  g_gi);
    cudaGetSymbolAddress((void**)&ghp,  g_gh);
    cudaGetSymbolAddress((void**)&w2pp, g_w2p);

    repack_w2<<<(D*D*17 + 255)/256, 256>>>(conv2_w);
    se_kernel<<<NTOK/8, 256>>>(x, w_se, b_se);

    dim3 g2(2, 16, NB), g6(6, 16, NB);
    // conv1: x @ conv1_w^T -> bn1+relu -> h1
    nt_gemm<0><<<g2, 256>>>(x, D, conv1_w, h1p, D, 0, D,
                            nullptr, bn1_g, bn1_b, bn1_m, bn1_v, nullptr);
    // msg: relu(x @ w_msg^T + b_msg)
    nt_gemm<2><<<g2, 256>>>(x, D, w_msg, msgp, D, 0, D,
                            b_msg, nullptr, nullptr, nullptr, nullptr, nullptr);
    // conv2 (17-tap) + bn2 + residual + relu -> x_in[:, :256]
    nt_gemm<1><<<g2, 256>>>(h1p, D, w2pp, xinp, 2*D, 0, D*17,
                            nullptr, bn2_g, bn2_b, bn2_m, bn2_v, x);
    // NMP -> x_in[:, 256:512]
    nmp_kernel<<<dim3(N_SEQ/64, NB), 256>>>(mask);
    // gi = x_in @ w_ih^T + b_ih
    nt_gemm<3><<<g6, 256>>>(xinp, 2*D, w_ih, gip, 3*D, 0, 2*D,
                            b_ih, nullptr, nullptr, nullptr, nullptr, nullptr);
    // gh = x @ w_hh^T + b_hh
    nt_gemm<3><<<g6, 256>>>(x, D, w_hh, ghp, 3*D, 0, D,
                            b_hh, nullptr, nullptr, nullptr, nullptr, nullptr);
    // GRU combine
    combine_kernel<<<(NTOK*64)/256, 256>>>(x, out);
}

// round 9
// speedup vs baseline: 1.9781x; 1.9781x over previous
#include <cuda_runtime.h>
#include <cuda_bf16.h>
#include <cstdint>
#include <math.h>

#define D 256
#define N_SEQ 2048
#define NB 16
#define NTOK (NB*N_SEQ)

// -------- scratch (device globals: allocation-guard safe) --------
__device__ float g_s4[NTOK*4];                    // (s0,s1,s2,|s|^2)
__device__ float g_msg[(size_t)NTOK*D];
__device__ float g_msgT[(size_t)NB*D*N_SEQ];      // msg transposed per batch
__device__ float g_h1[(size_t)NTOK*D];
__device__ float g_xin[(size_t)NTOK*2*D];
__device__ float g_gi[(size_t)NTOK*3*D];
__device__ float g_gh[(size_t)NTOK*3*D];
__device__ float g_w2p[D*D*17];                   // conv2_w repacked (o,k,i)

// ======================= helpers =======================
// bf16x3 split: x ~= hi + lo, hi = bf16(x), lo = bf16(x - hi)
__device__ __forceinline__ void split2(float x0, float x1, uint32_t& h, uint32_t& l){
    __nv_bfloat162 hh = __floats2bfloat162_rn(x0, x1);
    float r0 = x0 - __bfloat162float(hh.x);
    float r1 = x1 - __bfloat162float(hh.y);
    __nv_bfloat162 ll = __floats2bfloat162_rn(r0, r1);
    h = *(uint32_t*)&hh;
    l = *(uint32_t*)&ll;
}
__device__ __forceinline__ void mma16816(float* d, const uint32_t* a, const uint32_t* b){
    asm volatile(
        "mma.sync.aligned.m16n8k16.row.col.f32.bf16.bf16.f32 "
        "{%0,%1,%2,%3}, {%4,%5,%6,%7}, {%8,%9}, {%0,%1,%2,%3};"
        : "+f"(d[0]), "+f"(d[1]), "+f"(d[2]), "+f"(d[3])
        : "r"(a[0]), "r"(a[1]), "r"(a[2]), "r"(a[3]), "r"(b[0]), "r"(b[1]));
}

// ======================= small SIMT kernels =======================
__global__ void repack_w2(const float* __restrict__ w) {
    int idx = blockIdx.x*256 + threadIdx.x;
    if (idx < D*D*17) {
        int o = idx/(D*17); int r = idx%(D*17); int k = r/D; int i = r%D;
        g_w2p[idx] = w[(size_t)o*D*17 + (size_t)i*17 + k];
    }
}

__global__ void se_kernel(const float* __restrict__ x,
                          const float* __restrict__ w_se,
                          const float* __restrict__ b_se) {
    int tok = blockIdx.x*8 + (threadIdx.x>>5);
    int lane = threadIdx.x & 31;
    const float* xp = x + (size_t)tok*D;
    float d0=0.f, d1=0.f, d2=0.f;
    #pragma unroll
    for (int i=lane; i<D; i+=32) {
        float xv = xp[i];
        d0 += xv * w_se[i];
        d1 += xv * w_se[D+i];
        d2 += xv * w_se[2*D+i];
    }
    #pragma unroll
    for (int o=16; o; o>>=1) {
        d0 += __shfl_down_sync(0xffffffffu, d0, o);
        d1 += __shfl_down_sync(0xffffffffu, d1, o);
        d2 += __shfl_down_sync(0xffffffffu, d2, o);
    }
    if (lane==0) {
        float s0 = d0 + b_se[0], s1 = d1 + b_se[1], s2 = d2 + b_se[2];
        ((float4*)g_s4)[tok] = make_float4(s0, s1, s2, s0*s0 + s1*s1 + s2*s2);
    }
}

__global__ void transpose_msg() {
    __shared__ float ts[32][33];
    int b  = blockIdx.z;
    int t0 = blockIdx.x*32, d0 = blockIdx.y*32;
    int tx = threadIdx.x & 31, ty = threadIdx.x >> 5;
    #pragma unroll
    for (int k=0;k<4;k++)
        ts[ty+8*k][tx] = g_msg[((size_t)(b*N_SEQ) + t0+ty+8*k)*D + d0+tx];
    __syncthreads();
    #pragma unroll
    for (int k=0;k<4;k++)
        g_msgT[((size_t)b*D + d0+ty+8*k)*N_SEQ + t0+tx] = ts[tx][ty+8*k];
}

__device__ __forceinline__ float sigf(float a){ return 1.f/(1.f + __expf(-a)); }

__global__ void combine_kernel(const float* __restrict__ x, float* __restrict__ out) {
    int idx = blockIdx.x*256 + threadIdx.x;
    int tok = idx >> 6;
    int c4  = (idx & 63) * 4;
    const float* gi = g_gi + (size_t)tok*3*D;
    const float* gh = g_gh + (size_t)tok*3*D;
    float4 gir = *(const float4*)(gi + c4);
    float4 giz = *(const float4*)(gi + D + c4);
    float4 gin = *(const float4*)(gi + 2*D + c4);
    float4 ghr = *(const float4*)(gh + c4);
    float4 ghz = *(const float4*)(gh + D + c4);
    float4 ghn = *(const float4*)(gh + 2*D + c4);
    float4 xv  = *(const float4*)(x + (size_t)tok*D + c4);
    float4 o;
    { float r=sigf(gir.x+ghr.x), z=sigf(giz.x+ghz.x);
      o.x=(1.f-z)*tanhf(gin.x+r*ghn.x)+z*xv.x; }
    { float r=sigf(gir.y+ghr.y), z=sigf(giz.y+ghz.y);
      o.y=(1.f-z)*tanhf(gin.y+r*ghn.y)+z*xv.y; }
    { float r=sigf(gir.z+ghr.z), z=sigf(giz.z+ghz.z);
      o.z=(1.f-z)*tanhf(gin.z+r*ghn.z)+z*xv.z; }
    { float r=sigf(gir.w+ghr.w), z=sigf(giz.w+ghz.w);
      o.w=(1.f-z)*tanhf(gin.w+r*ghn.w)+z*xv.w; }
    *(float4*)(out + (size_t)tok*D + c4) = o;
}

// ======================= bf16x3 mma.sync GEMM =======================
// C[b, m, n] = sum_k A[b, m, k] * W[n, k]
// Block tile 128x128, BK=16, 8 warps (4 over M x 2 over N), warp tile 32x64.
// A*B ~= Ah*Bh + Al*Bh + Ah*Bl  (bf16 hi/lo split, fp32 accumulate)
// ASRC: 0 plain A; 1 conv2 im2col over h1; 2 NMP A = exp(-dist)*mask on the fly
// MODE: 0 bn+relu; 1 bn+residual+relu; 2 bias+relu; 3 bias; 4 plain
#define SRU 12   // row stride in uint32 (=24 bf16); (row*12+tig)%32 hits all banks once

template<int ASRC, int MODE, bool WBATCH>
__global__ __launch_bounds__(256, 2) void mm_gemm(
    const float* __restrict__ A, int lda,
    const float* __restrict__ W, int ldw,
    float* __restrict__ C, int ldc, int coff,
    int K,
    const float* __restrict__ bias,
    const float* __restrict__ bng, const float* __restrict__ bnb,
    const float* __restrict__ bnm, const float* __restrict__ bnv,
    const float* __restrict__ res,
    const float* __restrict__ mask)
{
    __shared__ uint32_t AsH[2][128*SRU];
    __shared__ uint32_t AsL[2][128*SRU];
    __shared__ uint32_t WsH[2][128*SRU];
    __shared__ uint32_t WsL[2][128*SRU];

    const int tid  = threadIdx.x;
    const int wid  = tid >> 5;
    const int lane = tid & 31;
    const int gid  = lane >> 2;     // group id (0..7)
    const int tig  = lane & 3;      // thread in group (0..3)
    const int wm   = wid & 3;       // warp M index 0..3
    const int wn   = wid >> 2;      // warp N index 0..1

    const int b  = blockIdx.z;
    const int m0 = blockIdx.y * 128;
    const int n0 = blockIdx.x * 128;
    const float* Ab = A + (size_t)b * N_SEQ * lda;
    const float* Wb = W + (WBATCH ? (size_t)b * 256 * (size_t)ldw : 0);

    const int row = tid >> 1;        // 0..127 (staging row)
    const int kb  = (tid & 1) * 8;   // staging k offset (0 or 8)
    const int ku  = kb >> 1;         // uint32 offset (0 or 4)

    float acc[2][8][4];
    #pragma unroll
    for (int mt=0;mt<2;mt++)
        #pragma unroll
        for (int nt=0;nt<8;nt++)
            #pragma unroll
            for (int e=0;e<4;e++) acc[mt][nt][e]=0.f;

    const int nchunk = K / 16;

    uint32_t raH[4], raL[4], rbH[4], rbL[4];

    auto loadA = [&](int c){
        const int kt = c * 16;
        float v[8];
        if (ASRC == 2) {
            float4 si = ((const float4*)g_s4)[b*N_SEQ + m0 + row];
            const float* mrow = mask + ((size_t)(b*N_SEQ) + m0 + row)*N_SEQ + kt + kb;
            float4 mk0 = *(const float4*)(mrow);
            float4 mk1 = *(const float4*)(mrow + 4);
            float mk[8] = {mk0.x,mk0.y,mk0.z,mk0.w,mk1.x,mk1.y,mk1.z,mk1.w};
            #pragma unroll
            for (int e = 0; e < 8; e++) {
                float4 sj = ((const float4*)g_s4)[b*N_SEQ + kt + kb + e];
                float dist = si.w + sj.w - 2.f*(si.x*sj.x + si.y*sj.y + si.z*sj.z);
                v[e] = __expf(-dist) * mk[e];
            }
        } else if (ASRC == 1) {
            #pragma unroll
            for (int h = 0; h < 2; h++) {
                int kk = kt + kb + 4*h;
                int tap = kk >> 8, ch = kk & 255;
                int srct = m0 + row + tap - 8;
                float4 t = (srct >= 0 && srct < N_SEQ)
                    ? *(const float4*)(Ab + (size_t)srct*lda + ch)
                    : make_float4(0.f,0.f,0.f,0.f);
                v[4*h+0]=t.x; v[4*h+1]=t.y; v[4*h+2]=t.z; v[4*h+3]=t.w;
            }
        } else {
            const float* p = Ab + (size_t)(m0+row)*lda + kt + kb;
            float4 t0 = *(const float4*)(p);
            float4 t1 = *(const float4*)(p + 4);
            v[0]=t0.x; v[1]=t0.y; v[2]=t0.z; v[3]=t0.w;
            v[4]=t1.x; v[5]=t1.y; v[6]=t1.z; v[7]=t1.w;
        }
        #pragma unroll
        for (int i = 0; i < 4; i++) split2(v[2*i], v[2*i+1], raH[i], raL[i]);
    };
    auto loadB = [&](int c){
        const int kt = c * 16;
        const float* p = Wb + (size_t)(n0+row)*ldw + kt + kb;
        float4 t0 = *(const float4*)(p);
        float4 t1 = *(const float4*)(p + 4);
        float v[8] = {t0.x,t0.y,t0.z,t0.w,t1.x,t1.y,t1.z,t1.w};
        #pragma unroll
        for (int i = 0; i < 4; i++) split2(v[2*i], v[2*i+1], rbH[i], rbL[i]);
    };
    auto store = [&](int s){
        uint32_t base = row*SRU + ku;
        *(uint4*)&AsH[s][base] = make_uint4(raH[0],raH[1],raH[2],raH[3]);
        *(uint4*)&AsL[s][base] = make_uint4(raL[0],raL[1],raL[2],raL[3]);
        *(uint4*)&WsH[s][base] = make_uint4(rbH[0],rbH[1],rbH[2],rbH[3]);
        *(uint4*)&WsL[s][base] = make_uint4(rbL[0],rbL[1],rbL[2],rbL[3]);
    };

    loadA(0); loadB(0);
    store(0);
    __syncthreads();

    for (int c = 0; c < nchunk; c++) {
        const int s = c & 1;
        if (c + 1 < nchunk) { loadA(c+1); loadB(c+1); }

        uint32_t afH[2][4], afL[2][4];
        #pragma unroll
        for (int mt = 0; mt < 2; mt++) {
            int ar = wm*32 + mt*16 + gid;
            afH[mt][0] = AsH[s][ar*SRU + tig];
            afH[mt][1] = AsH[s][(ar+8)*SRU + tig];
            afH[mt][2] = AsH[s][ar*SRU + tig + 4];
            afH[mt][3] = AsH[s][(ar+8)*SRU + tig + 4];
            afL[mt][0] = AsL[s][ar*SRU + tig];
            afL[mt][1] = AsL[s][(ar+8)*SRU + tig];
            afL[mt][2] = AsL[s][ar*SRU + tig + 4];
            afL[mt][3] = AsL[s][(ar+8)*SRU + tig + 4];
        }
        #pragma unroll
        for (int nt = 0; nt < 8; nt++) {
            int br = wn*64 + nt*8 + gid;
            uint32_t bfH[2], bfL[2];
            bfH[0] = WsH[s][br*SRU + tig];
            bfH[1] = WsH[s][br*SRU + tig + 4];
            bfL[0] = WsL[s][br*SRU + tig];
            bfL[1] = WsL[s][br*SRU + tig + 4];
            #pragma unroll
            for (int mt = 0; mt < 2; mt++) {
                mma16816(acc[mt][nt], afH[mt], bfH);
                mma16816(acc[mt][nt], afL[mt], bfH);
                mma16816(acc[mt][nt], afH[mt], bfL);
            }
        }

        if (c + 1 < nchunk) {
            store(s ^ 1);
            __syncthreads();
        }
    }

    // ---- epilogue ----
    #pragma unroll
    for (int mt = 0; mt < 2; mt++) {
        #pragma unroll
        for (int half = 0; half < 2; half++) {
            int m = m0 + wm*32 + mt*16 + gid + half*8;
            float* Crow = C + ((size_t)(b*N_SEQ) + m)*ldc + coff;
            const float* resrow = (MODE==1) ? res + ((size_t)(b*N_SEQ) + m)*256 : (const float*)0;
            #pragma unroll
            for (int nt = 0; nt < 8; nt++) {
                int n = n0 + wn*64 + nt*8 + tig*2;
                float v0 = acc[mt][nt][half*2+0];
                float v1 = acc[mt][nt][half*2+1];
                if (MODE == 0 || MODE == 1) {
                    float r0 = 0.f, r1 = 0.f;
                    if (MODE == 1) {
                        float2 rv = *(const float2*)(resrow + n);
                        r0 = rv.x; r1 = rv.y;
                    }
                    float sc0 = bng[n+0]*rsqrtf(bnv[n+0]+1e-5f);
                    float sc1 = bng[n+1]*rsqrtf(bnv[n+1]+1e-5f);
                    v0 = fmaxf(v0*sc0 + (bnb[n+0]-bnm[n+0]*sc0) + r0, 0.f);
                    v1 = fmaxf(v1*sc1 + (bnb[n+1]-bnm[n+1]*sc1) + r1, 0.f);
                } else if (MODE == 2) {
                    v0 = fmaxf(v0 + bias[n+0], 0.f);
                    v1 = fmaxf(v1 + bias[n+1], 0.f);
                } else if (MODE == 3) {
                    v0 += bias[n+0];
                    v1 += bias[n+1];
                }
                *(float2*)(Crow + n) = make_float2(v0, v1);
            }
        }
    }
}

// ======================= launch =======================
extern "C" void kernel_launch(void* const* d_in, const int* in_sizes, int n_in,
                              void* d_out, int out_size) {
    (void)in_sizes; (void)n_in; (void)out_size;
    const float* x       = (const float*)d_in[0];
    const float* mask    = (const float*)d_in[1];
    const float* w_se    = (const float*)d_in[2];
    const float* b_se    = (const float*)d_in[3];
    const float* conv1_w = (const float*)d_in[4];
    const float* bn1_g   = (const float*)d_in[5];
    const float* bn1_b   = (const float*)d_in[6];
    const float* bn1_m   = (const float*)d_in[7];
    const float* bn1_v   = (const float*)d_in[8];
    const float* conv2_w = (const float*)d_in[9];
    const float* bn2_g   = (const float*)d_in[10];
    const float* bn2_b   = (const float*)d_in[11];
    const float* bn2_m   = (const float*)d_in[12];
    const float* bn2_v   = (const float*)d_in[13];
    const float* w_msg   = (const float*)d_in[14];
    const float* b_msg   = (const float*)d_in[15];
    const float* w_ih    = (const float*)d_in[16];
    const float* b_ih    = (const float*)d_in[17];
    const float* w_hh    = (const float*)d_in[18];
    const float* b_hh    = (const float*)d_in[19];
    float* out = (float*)d_out;

    float *h1p, *msgp, *msgTp, *xinp, *gip, *ghp, *w2pp;
    cudaGetSymbolAddress((void**)&h1p,   g_h1);
    cudaGetSymbolAddress((void**)&msgp,  g_msg);
    cudaGetSymbolAddress((void**)&msgTp, g_msgT);
    cudaGetSymbolAddress((void**)&xinp,  g_xin);
    cudaGetSymbolAddress((void**)&gip,   g_gi);
    cudaGetSymbolAddress((void**)&ghp,   g_gh);
    cudaGetSymbolAddress((void**)&w2pp,  g_w2p);

    repack_w2<<<(D*D*17 + 255)/256, 256>>>(conv2_w);
    se_kernel<<<NTOK/8, 256>>>(x, w_se, b_se);

    dim3 g2(2, 16, NB), g6(6, 16, NB);
    // conv1: x @ conv1_w^T -> bn1+relu -> h1
    mm_gemm<0,0,false><<<g2, 256>>>(x, D, conv1_w, D, h1p, D, 0, D,
        nullptr, bn1_g, bn1_b, bn1_m, bn1_v, nullptr, nullptr);
    // msg: relu(x @ w_msg^T + b_msg)
    mm_gemm<0,2,false><<<g2, 256>>>(x, D, w_msg, D, msgp, D, 0, D,
        b_msg, nullptr, nullptr, nullptr, nullptr, nullptr, nullptr);
    transpose_msg<<<dim3(N_SEQ/32, D/32, NB), 256>>>();
    // conv2 (17-tap im2col) + bn2 + residual + relu -> x_in[:, :256]
    mm_gemm<1,1,false><<<g2, 256>>>(h1p, D, w2pp, D*17, xinp, 2*D, 0, D*17,
        nullptr, bn2_g, bn2_b, bn2_m, bn2_v, x, nullptr);
    // NMP: x_nmp = (exp(-dist)*mask) @ msg -> x_in[:, 256:512]
    mm_gemm<2,4,true><<<g2, 256>>>(x, D, msgTp, N_SEQ, xinp, 2*D, D, N_SEQ,
        nullptr, nullptr, nullptr, nullptr, nullptr, nullptr, mask);
    // gh = x @ w_hh^T + b_hh
    mm_gemm<0,3,false><<<g6, 256>>>(x, D, w_hh, D, ghp, 3*D, 0, D,
        b_hh, nullptr, nullptr, nullptr, nullptr, nullptr, nullptr);
    // gi = x_in @ w_ih^T + b_ih
    mm_gemm<0,3,false><<<g6, 256>>>(xinp, 2*D, w_ih, 2*D, gip, 3*D, 0, 2*D,
        b_ih, nullptr, nullptr, nullptr, nullptr, nullptr, nullptr);
    // GRU combine
    combine_kernel<<<(NTOK*64)/256, 256>>>(x, out);
}

// round 10
// speedup vs baseline: 2.5215x; 1.2747x over previous
#include <cuda_runtime.h>
#include <cuda_bf16.h>
#include <cstdint>
#include <math.h>

#define D 256
#define N_SEQ 2048
#define NB 16
#define NTOK (NB*N_SEQ)

// -------- persistent scratch (device globals) --------
__device__ float g_s4[NTOK*4];                        // (s0,s1,s2,|s|^2)
__device__ float g_msg[(size_t)NTOK*D];               // msg fp32 (for transpose)
__device__ float g_gi[(size_t)NTOK*3*D];
__device__ float g_gh[(size_t)NTOK*3*D];

// bf16 hi/lo planes
__device__ __nv_bfloat16 g_xH[(size_t)NTOK*D],   g_xL[(size_t)NTOK*D];
__device__ __nv_bfloat16 g_h1H[(size_t)NTOK*D],  g_h1L[(size_t)NTOK*D];
__device__ __nv_bfloat16 g_xinH[(size_t)NTOK*2*D], g_xinL[(size_t)NTOK*2*D];
__device__ __nv_bfloat16 g_mtH[(size_t)NB*D*N_SEQ], g_mtL[(size_t)NB*D*N_SEQ];
__device__ __nv_bfloat16 g_w1H[D*D],      g_w1L[D*D];
__device__ __nv_bfloat16 g_wmH[D*D],      g_wmL[D*D];
__device__ __nv_bfloat16 g_whhH[3*D*D],   g_whhL[3*D*D];
__device__ __nv_bfloat16 g_wihH[3*D*2*D], g_wihL[3*D*2*D];
__device__ __nv_bfloat16 g_w2H[D*D*17],   g_w2L[D*D*17];

// ======================= asm helpers =======================
__device__ __forceinline__ void cpa(uint32_t d, const void* s, int sz){
    asm volatile("cp.async.cg.shared.global [%0], [%1], 16, %2;"
                 :: "r"(d), "l"(s), "r"(sz) : "memory");
}
#define CP_COMMIT() asm volatile("cp.async.commit_group;" ::: "memory")
#define CP_WAIT1()  asm volatile("cp.async.wait_group 1;" ::: "memory")

__device__ __forceinline__ void ldsm4(uint32_t& r0,uint32_t& r1,uint32_t& r2,uint32_t& r3,uint32_t a){
    asm volatile("ldmatrix.sync.aligned.m8n8.x4.shared.b16 {%0,%1,%2,%3}, [%4];"
                 : "=r"(r0),"=r"(r1),"=r"(r2),"=r"(r3) : "r"(a));
}
__device__ __forceinline__ void mma16816(float* d, const uint32_t* a, const uint32_t* b){
    asm volatile(
        "mma.sync.aligned.m16n8k16.row.col.f32.bf16.bf16.f32 "
        "{%0,%1,%2,%3}, {%4,%5,%6,%7}, {%8,%9}, {%0,%1,%2,%3};"
        : "+f"(d[0]), "+f"(d[1]), "+f"(d[2]), "+f"(d[3])
        : "r"(a[0]), "r"(a[1]), "r"(a[2]), "r"(a[3]), "r"(b[0]), "r"(b[1]));
}
// bf16 hi/lo split of a pair -> packed u32 each
__device__ __forceinline__ void split2(float x0, float x1, uint32_t& h, uint32_t& l){
    __nv_bfloat162 hh = __floats2bfloat162_rn(x0, x1);
    float r0 = x0 - __bfloat162float(hh.x);
    float r1 = x1 - __bfloat162float(hh.y);
    __nv_bfloat162 ll = __floats2bfloat162_rn(r0, r1);
    h = *(uint32_t*)&hh; l = *(uint32_t*)&ll;
}

// smem pipeline layout: 48B row stride, 128 rows per plane => 6144 B
#define PLANE 6144
#define STAGE (4*PLANE)          // AH, AL, WH, WL
#define SMEM_BYTES (3*STAGE)     // 73728

// ======================= prep kernels =======================
__global__ void split_arr(const float* __restrict__ s, __nv_bfloat16* __restrict__ H,
                          __nv_bfloat16* __restrict__ L, int n){
    int i = blockIdx.x*256 + threadIdx.x;
    if (i < n){
        float v = s[i];
        __nv_bfloat16 h = __float2bfloat16(v);
        H[i] = h; L[i] = __float2bfloat16(v - __bfloat162float(h));
    }
}
__global__ void repack_w2_split(const float* __restrict__ w){
    int idx = blockIdx.x*256 + threadIdx.x;
    if (idx < D*D*17){
        int o = idx/(D*17); int r = idx%(D*17); int k = r/D; int i = r%D;
        float v = w[(size_t)o*D*17 + (size_t)i*17 + k];
        __nv_bfloat16 h = __float2bfloat16(v);
        g_w2H[idx] = h; g_w2L[idx] = __float2bfloat16(v - __bfloat162float(h));
    }
}
__global__ void se_kernel(const float* __restrict__ x,
                          const float* __restrict__ w_se,
                          const float* __restrict__ b_se){
    int tok = blockIdx.x*8 + (threadIdx.x>>5);
    int lane = threadIdx.x & 31;
    const float* xp = x + (size_t)tok*D;
    float d0=0.f, d1=0.f, d2=0.f;
    #pragma unroll
    for (int i=lane; i<D; i+=32){
        float xv = xp[i];
        d0 += xv*w_se[i]; d1 += xv*w_se[D+i]; d2 += xv*w_se[2*D+i];
    }
    #pragma unroll
    for (int o=16;o;o>>=1){
        d0 += __shfl_down_sync(0xffffffffu,d0,o);
        d1 += __shfl_down_sync(0xffffffffu,d1,o);
        d2 += __shfl_down_sync(0xffffffffu,d2,o);
    }
    if (lane==0){
        float s0=d0+b_se[0], s1=d1+b_se[1], s2=d2+b_se[2];
        ((float4*)g_s4)[tok] = make_float4(s0,s1,s2, s0*s0+s1*s1+s2*s2);
    }
}
__global__ void transpose_msg(){
    __shared__ float ts[32][33];
    int b = blockIdx.z;
    int t0 = blockIdx.x*32, d0 = blockIdx.y*32;
    int tx = threadIdx.x & 31, ty = threadIdx.x >> 5;
    #pragma unroll
    for (int k=0;k<4;k++)
        ts[ty+8*k][tx] = g_msg[((size_t)(b*N_SEQ) + t0+ty+8*k)*D + d0+tx];
    __syncthreads();
    #pragma unroll
    for (int k=0;k<4;k++){
        float v = ts[tx][ty+8*k];
        size_t o = ((size_t)b*D + d0+ty+8*k)*N_SEQ + t0+tx;
        __nv_bfloat16 h = __float2bfloat16(v);
        g_mtH[o] = h; g_mtL[o] = __float2bfloat16(v - __bfloat162float(h));
    }
}
__device__ __forceinline__ float sigf(float a){ return 1.f/(1.f + __expf(-a)); }
__global__ void combine_kernel(const float* __restrict__ x, float* __restrict__ out){
    int idx = blockIdx.x*256 + threadIdx.x;
    int tok = idx >> 6;
    int c4  = (idx & 63)*4;
    const float* gi = g_gi + (size_t)tok*3*D;
    const float* gh = g_gh + (size_t)tok*3*D;
    float4 gir=*(const float4*)(gi+c4), giz=*(const float4*)(gi+D+c4), gin=*(const float4*)(gi+2*D+c4);
    float4 ghr=*(const float4*)(gh+c4), ghz=*(const float4*)(gh+D+c4), ghn=*(const float4*)(gh+2*D+c4);
    float4 xv =*(const float4*)(x + (size_t)tok*D + c4);
    float4 o;
    { float r=sigf(gir.x+ghr.x), z=sigf(giz.x+ghz.x); o.x=(1.f-z)*tanhf(gin.x+r*ghn.x)+z*xv.x; }
    { float r=sigf(gir.y+ghr.y), z=sigf(giz.y+ghz.y); o.y=(1.f-z)*tanhf(gin.y+r*ghn.y)+z*xv.y; }
    { float r=sigf(gir.z+ghr.z), z=sigf(giz.z+ghz.z); o.z=(1.f-z)*tanhf(gin.z+r*ghn.z)+z*xv.z; }
    { float r=sigf(gir.w+ghr.w), z=sigf(giz.w+ghz.w); o.w=(1.f-z)*tanhf(gin.w+r*ghn.w)+z*xv.w; }
    *(float4*)(out + (size_t)tok*D + c4) = o;
}

// ======================= bf16x3 GEMM (cp.async + ldmatrix) =======================
// C[b,m,n] = sum_k A[b,m,k]*W[n,k]; block tile 128x128, BK=16, 8 warps (4M x 2N).
// A*B ~= Ah*Bh + Al*Bh + Ah*Bl, fp32 accum. Operands are pre-split bf16 planes.
// ASRC: 0 plain planes; 1 conv2 im2col over h1 planes; 2 NMP on-the-fly A (STS)
// MODE: 0 bn+relu; 1 bn+residual+relu; 2 bias+relu; 3 bias; 4 plain
// OUTHL: epilogue writes bf16 hi/lo planes (CH/CL), else fp32 (Cf)
template<int ASRC, int MODE, bool WBATCH, bool OUTHL>
__global__ __launch_bounds__(256, 2) void mm_gemm(
    const __nv_bfloat16* __restrict__ AHp, const __nv_bfloat16* __restrict__ ALp, int lda,
    const __nv_bfloat16* __restrict__ WHp, const __nv_bfloat16* __restrict__ WLp, int ldw,
    float* __restrict__ Cf, __nv_bfloat16* __restrict__ CH, __nv_bfloat16* __restrict__ CL,
    int ldc, int coff, int K,
    const float* __restrict__ bias,
    const float* __restrict__ bng, const float* __restrict__ bnb,
    const float* __restrict__ bnm, const float* __restrict__ bnv,
    const float* __restrict__ res,
    const float* __restrict__ mask)
{
    extern __shared__ char sm[];
    const uint32_t smb = (uint32_t)__cvta_generic_to_shared(sm);

    const int tid  = threadIdx.x;
    const int wid  = tid >> 5;
    const int lane = tid & 31;
    const int gid  = lane >> 2;
    const int tig  = lane & 3;
    const int wm   = wid & 3;
    const int wn   = wid >> 2;

    const int b  = blockIdx.z;
    const int m0 = blockIdx.y * 128;
    const int n0 = blockIdx.x * 128;

    const __nv_bfloat16* AHb = (ASRC==1) ? AHp : AHp + (size_t)b*N_SEQ*lda;
    const __nv_bfloat16* ALb = (ASRC==1) ? ALp : ALp + (size_t)b*N_SEQ*lda;
    const __nv_bfloat16* AH1 = AHp + (size_t)b*N_SEQ*256;   // conv2: h1 planes
    const __nv_bfloat16* AL1 = ALp + (size_t)b*N_SEQ*256;
    const __nv_bfloat16* WHb = WHp + (WBATCH ? (size_t)b*256*(size_t)ldw : 0);
    const __nv_bfloat16* WLb = WLp + (WBATCH ? (size_t)b*256*(size_t)ldw : 0);

    const int row  = tid >> 1;       // staging row 0..127
    const int half = tid & 1;        // 16B half (k 0..7 / 8..15)
    const int nchunk = K / 16;

    float acc[2][8][4];
    #pragma unroll
    for (int mt=0;mt<2;mt++)
        #pragma unroll
        for (int nt=0;nt<8;nt++)
            #pragma unroll
            for (int e=0;e<4;e++) acc[mt][nt][e]=0.f;

    // staging destinations (per-thread, stage-relative)
    const uint32_t dAH = row*48 + half*16;
    const uint32_t dAL = PLANE   + dAH;
    const uint32_t dWH = 2*PLANE + dAH;
    const uint32_t dWL = 3*PLANE + dAH;

    auto issue = [&](int c){
        const uint32_t sb = smb + (c%3)*STAGE;
        const int kt = c*16;
        const int kk = kt + half*8;
        if (ASRC == 0){
            const size_t ao = (size_t)(m0+row)*lda + kk;
            cpa(sb + dAH, AHb + ao, 16);
            cpa(sb + dAL, ALb + ao, 16);
        } else if (ASRC == 1){
            const int tap = kk >> 8;
            const int ch  = kk & 255;
            int srct = m0 + row + tap - 8;
            const int ok = (srct >= 0 && srct < N_SEQ) ? 16 : 0;
            srct = srct < 0 ? 0 : (srct >= N_SEQ ? N_SEQ-1 : srct);
            const size_t ao = (size_t)srct*256 + ch;
            cpa(sb + dAH, AH1 + ao, ok);
            cpa(sb + dAL, AL1 + ao, ok);
        } else {
            // NMP: A tile computed on the fly (STS, not cp.async)
            float4 si = ((const float4*)g_s4)[b*N_SEQ + m0 + row];
            const float* mrow = mask + ((size_t)(b*N_SEQ) + m0 + row)*N_SEQ + kk;
            float4 mk0 = *(const float4*)(mrow);
            float4 mk1 = *(const float4*)(mrow + 4);
            float mk[8] = {mk0.x,mk0.y,mk0.z,mk0.w,mk1.x,mk1.y,mk1.z,mk1.w};
            float v[8];
            #pragma unroll
            for (int e=0;e<8;e++){
                float4 sj = ((const float4*)g_s4)[b*N_SEQ + kk + e];
                float dist = si.w + sj.w - 2.f*(si.x*sj.x + si.y*sj.y + si.z*sj.z);
                v[e] = __expf(-dist) * mk[e];
            }
            uint32_t h[4], l[4];
            #pragma unroll
            for (int i=0;i<4;i++) split2(v[2*i], v[2*i+1], h[i], l[i]);
            uint32_t da = sb + dAH, dl = sb + dAL;
            asm volatile("st.shared.v4.b32 [%0], {%1,%2,%3,%4};"
                         :: "r"(da), "r"(h[0]),"r"(h[1]),"r"(h[2]),"r"(h[3]) : "memory");
            asm volatile("st.shared.v4.b32 [%0], {%1,%2,%3,%4};"
                         :: "r"(dl), "r"(l[0]),"r"(l[1]),"r"(l[2]),"r"(l[3]) : "memory");
        }
        const size_t wo = (size_t)(n0+row)*ldw + kk;
        cpa(sb + dWH, WHb + wo, 16);
        cpa(sb + dWL, WLb + wo, 16);
    };

    // ldmatrix lane addressing (stage-relative byte offsets)
    const uint32_t arow = (lane & 7) + (lane & 8);       // +0..7, +8..15
    const uint32_t aoff = ((lane >> 4) & 1) * 16;        // k half
    const uint32_t brow = (lane & 7) + ((lane & 16) ? 8 : 0);
    const uint32_t boff = ((lane >> 3) & 1) * 16;
    uint32_t aAddr[2], bAddr[4];
    #pragma unroll
    for (int mt=0;mt<2;mt++)
        aAddr[mt] = (wm*32 + mt*16 + arow)*48 + aoff;
    #pragma unroll
    for (int ntp=0;ntp<4;ntp++)
        bAddr[ntp] = (wn*64 + ntp*16 + brow)*48 + boff;

    // prologue: stages 0 and 1
    issue(0); CP_COMMIT();
    issue(1); CP_COMMIT();

    for (int c = 0; c < nchunk; c++){
        CP_WAIT1();
        __syncthreads();
        const uint32_t sb = smb + (c%3)*STAGE;

        uint32_t afH[2][4], afL[2][4];
        #pragma unroll
        for (int mt=0;mt<2;mt++){
            ldsm4(afH[mt][0],afH[mt][1],afH[mt][2],afH[mt][3], sb + aAddr[mt]);
            ldsm4(afL[mt][0],afL[mt][1],afL[mt][2],afL[mt][3], sb + PLANE + aAddr[mt]);
        }
        #pragma unroll
        for (int ntp=0;ntp<4;ntp++){
            uint32_t h0,h1,h2,h3, l0,l1,l2,l3;
            ldsm4(h0,h1,h2,h3, sb + 2*PLANE + bAddr[ntp]);
            ldsm4(l0,l1,l2,l3, sb + 3*PLANE + bAddr[ntp]);
            uint32_t bH0[2]={h0,h1}, bH1[2]={h2,h3}, bL0[2]={l0,l1}, bL1[2]={l2,l3};
            #pragma unroll
            for (int mt=0;mt<2;mt++){
                mma16816(acc[mt][2*ntp+0], afH[mt], bH0);
                mma16816(acc[mt][2*ntp+0], afL[mt], bH0);
                mma16816(acc[mt][2*ntp+0], afH[mt], bL0);
                mma16816(acc[mt][2*ntp+1], afH[mt], bH1);
                mma16816(acc[mt][2*ntp+1], afL[mt], bH1);
                mma16816(acc[mt][2*ntp+1], afH[mt], bL1);
            }
        }

        if (c + 2 < nchunk) issue(c+2);
        CP_COMMIT();
    }

    // ---- epilogue ----
    #pragma unroll
    for (int mt=0;mt<2;mt++){
        #pragma unroll
        for (int hf=0;hf<2;hf++){
            const int m = m0 + wm*32 + mt*16 + gid + hf*8;
            const size_t rb = (size_t)(b*N_SEQ) + m;
            float* Crow = Cf ? Cf + rb*ldc + coff : (float*)0;
            const float* resrow = (MODE==1) ? res + rb*256 : (const float*)0;
            #pragma unroll
            for (int nt=0;nt<8;nt++){
                const int n = n0 + wn*64 + nt*8 + tig*2;
                float v0 = acc[mt][nt][hf*2+0];
                float v1 = acc[mt][nt][hf*2+1];
                if (MODE == 0 || MODE == 1){
                    float r0=0.f, r1=0.f;
                    if (MODE == 1){
                        float2 rv = *(const float2*)(resrow + n);
                        r0 = rv.x; r1 = rv.y;
                    }
                    float sc0 = bng[n+0]*rsqrtf(bnv[n+0]+1e-5f);
                    float sc1 = bng[n+1]*rsqrtf(bnv[n+1]+1e-5f);
                    v0 = fmaxf(v0*sc0 + (bnb[n+0]-bnm[n+0]*sc0) + r0, 0.f);
                    v1 = fmaxf(v1*sc1 + (bnb[n+1]-bnm[n+1]*sc1) + r1, 0.f);
                } else if (MODE == 2){
                    v0 = fmaxf(v0 + bias[n+0], 0.f);
                    v1 = fmaxf(v1 + bias[n+1], 0.f);
                } else if (MODE == 3){
                    v0 += bias[n+0]; v1 += bias[n+1];
                }
                if (OUTHL){
                    __nv_bfloat162 h2 = __floats2bfloat162_rn(v0, v1);
                    float q0 = v0 - __bfloat162float(h2.x);
                    float q1 = v1 - __bfloat162float(h2.y);
                    __nv_bfloat162 l2 = __floats2bfloat162_rn(q0, q1);
                    *(__nv_bfloat162*)(CH + rb*ldc + coff + n) = h2;
                    *(__nv_bfloat162*)(CL + rb*ldc + coff + n) = l2;
                } else {
                    *(float2*)(Crow + n) = make_float2(v0, v1);
                }
            }
        }
    }
}

// ======================= launch =======================
extern "C" void kernel_launch(void* const* d_in, const int* in_sizes, int n_in,
                              void* d_out, int out_size){
    (void)in_sizes; (void)n_in; (void)out_size;
    const float* x       = (const float*)d_in[0];
    const float* mask    = (const float*)d_in[1];
    const float* w_se    = (const float*)d_in[2];
    const float* b_se    = (const float*)d_in[3];
    const float* conv1_w = (const float*)d_in[4];
    const float* bn1_g   = (const float*)d_in[5];
    const float* bn1_b   = (const float*)d_in[6];
    const float* bn1_m   = (const float*)d_in[7];
    const float* bn1_v   = (const float*)d_in[8];
    const float* conv2_w = (const float*)d_in[9];
    const float* bn2_g   = (const float*)d_in[10];
    const float* bn2_b   = (const float*)d_in[11];
    const float* bn2_m   = (const float*)d_in[12];
    const float* bn2_v   = (const float*)d_in[13];
    const float* w_msg   = (const float*)d_in[14];
    const float* b_msg   = (const float*)d_in[15];
    const float* w_ih    = (const float*)d_in[16];
    const float* b_ih    = (const float*)d_in[17];
    const float* w_hh    = (const float*)d_in[18];
    const float* b_hh    = (const float*)d_in[19];
    float* out = (float*)d_out;

    __nv_bfloat16 *xH,*xL,*h1H,*h1L,*xinH,*xinL,*mtH,*mtL;
    __nv_bfloat16 *w1H,*w1L,*wmH,*wmL,*whhH,*whhL,*wihH,*wihL,*w2H,*w2L;
    float *msgp,*gip,*ghp;
    cudaGetSymbolAddress((void**)&xH, g_xH);   cudaGetSymbolAddress((void**)&xL, g_xL);
    cudaGetSymbolAddress((void**)&h1H, g_h1H); cudaGetSymbolAddress((void**)&h1L, g_h1L);
    cudaGetSymbolAddress((void**)&xinH, g_xinH); cudaGetSymbolAddress((void**)&xinL, g_xinL);
    cudaGetSymbolAddress((void**)&mtH, g_mtH); cudaGetSymbolAddress((void**)&mtL, g_mtL);
    cudaGetSymbolAddress((void**)&w1H, g_w1H); cudaGetSymbolAddress((void**)&w1L, g_w1L);
    cudaGetSymbolAddress((void**)&wmH, g_wmH); cudaGetSymbolAddress((void**)&wmL, g_wmL);
    cudaGetSymbolAddress((void**)&whhH, g_whhH); cudaGetSymbolAddress((void**)&whhL, g_whhL);
    cudaGetSymbolAddress((void**)&wihH, g_wihH); cudaGetSymbolAddress((void**)&wihL, g_wihL);
    cudaGetSymbolAddress((void**)&w2H, g_w2H); cudaGetSymbolAddress((void**)&w2L, g_w2L);
    cudaGetSymbolAddress((void**)&msgp, g_msg);
    cudaGetSymbolAddress((void**)&gip, g_gi);
    cudaGetSymbolAddress((void**)&ghp, g_gh);

    cudaFuncSetAttribute(mm_gemm<0,0,false,true>,  cudaFuncAttributeMaxDynamicSharedMemorySize, SMEM_BYTES);
    cudaFuncSetAttribute(mm_gemm<0,2,false,false>, cudaFuncAttributeMaxDynamicSharedMemorySize, SMEM_BYTES);
    cudaFuncSetAttribute(mm_gemm<1,1,false,true>,  cudaFuncAttributeMaxDynamicSharedMemorySize, SMEM_BYTES);
    cudaFuncSetAttribute(mm_gemm<2,4,true,true>,   cudaFuncAttributeMaxDynamicSharedMemorySize, SMEM_BYTES);
    cudaFuncSetAttribute(mm_gemm<0,3,false,false>, cudaFuncAttributeMaxDynamicSharedMemorySize, SMEM_BYTES);

    // prep: splits + s-embedding
    split_arr<<<(NTOK*D+255)/256,256>>>(x, xH, xL, NTOK*D);
    split_arr<<<(D*D+255)/256,256>>>(conv1_w, w1H, w1L, D*D);
    split_arr<<<(D*D+255)/256,256>>>(w_msg, wmH, wmL, D*D);
    split_arr<<<(3*D*D+255)/256,256>>>(w_hh, whhH, whhL, 3*D*D);
    split_arr<<<(3*D*2*D+255)/256,256>>>(w_ih, wihH, wihL, 3*D*2*D);
    repack_w2_split<<<(D*D*17+255)/256,256>>>(conv2_w);
    se_kernel<<<NTOK/8,256>>>(x, w_se, b_se);

    dim3 g2(2,16,NB), g6(6,16,NB);
    // conv1 -> bn1+relu -> h1 planes
    mm_gemm<0,0,false,true><<<g2,256,SMEM_BYTES>>>(xH, xL, D, w1H, w1L, D,
        nullptr, h1H, h1L, D, 0, D, nullptr, bn1_g, bn1_b, bn1_m, bn1_v, nullptr, nullptr);
    // msg = relu(x@w_msg^T+b) -> fp32 (for transpose)
    mm_gemm<0,2,false,false><<<g2,256,SMEM_BYTES>>>(xH, xL, D, wmH, wmL, D,
        msgp, nullptr, nullptr, D, 0, D, b_msg, nullptr,nullptr,nullptr,nullptr, nullptr, nullptr);
    transpose_msg<<<dim3(N_SEQ/32, D/32, NB),256>>>();
    // conv2 (im2col over h1 planes) + bn2 + residual(x) + relu -> xin[:,0:256] planes
    mm_gemm<1,1,false,true><<<g2,256,SMEM_BYTES>>>(h1H, h1L, D, w2H, w2L, D*17,
        nullptr, xinH, xinL, 2*D, 0, D*17, nullptr, bn2_g, bn2_b, bn2_m, bn2_v, x, nullptr);
    // NMP: (exp(-dist)*mask) @ msg -> xin[:,256:512] planes
    mm_gemm<2,4,true,true><<<g2,256,SMEM_BYTES>>>(nullptr, nullptr, 0, mtH, mtL, N_SEQ,
        nullptr, xinH, xinL, 2*D, D, N_SEQ, nullptr, nullptr,nullptr,nullptr,nullptr, nullptr, mask);
    // gh = x @ w_hh^T + b_hh (fp32)
    mm_gemm<0,3,false,false><<<g6,256,SMEM_BYTES>>>(xH, xL, D, whhH, whhL, D,
        ghp, nullptr, nullptr, 3*D, 0, D, b_hh, nullptr,nullptr,nullptr,nullptr, nullptr, nullptr);
    // gi = xin @ w_ih^T + b_ih (fp32)
    mm_gemm<0,3,false,false><<<g6,256,SMEM_BYTES>>>(xinH, xinL, 2*D, wihH, wihL, 2*D,
        gip, nullptr, nullptr, 3*D, 0, 2*D, b_ih, nullptr,nullptr,nullptr,nullptr, nullptr, nullptr);
    // GRU combine
    combine_kernel<<<(NTOK*64)/256,256>>>(x, out);
}